// round 14
// baseline (speedup 1.0000x reference)
#include <cuda_runtime.h>
#include <cuda_bf16.h>
#include <math.h>
#include <stdint.h>

// Problem constants
#define B_  8
#define C_  256
#define H_  64
#define W_  64
#define HW_ 4096
#define NPIX 32768

// Scratch
__device__ float    g_qk[(size_t)NPIX * 64];      // fp32 q(32)|k(32), pixel-major
__device__ uint32_t g_vb[(size_t)NPIX * 128];     // bf16x2 v (256ch), pixel-major
__device__ uint4    g_wb4[320 * 32];              // bf16 W, [n][256ch], n-order q|k|v
__device__ uint4    g_attn4[(size_t)NPIX * 9 / 4]; // softmaxed weights [pix][9] fp32

#define SWZ(o) ((o) ^ (((o) >> 3) & 0x70))

__device__ __forceinline__ uint32_t pack_bf16(float lo, float hi) {
    uint32_t l = (uint32_t)__bfloat16_as_ushort(__float2bfloat16_rn(lo));
    uint32_t h = (uint32_t)__bfloat16_as_ushort(__float2bfloat16_rn(hi));
    return (h << 16) | l;
}

__device__ __forceinline__ void cp16(uint32_t dst, const void* src) {
    asm volatile("cp.async.cg.shared.global [%0], [%1], 16;" :: "r"(dst), "l"(src) : "memory");
}

// ---------------------------------------------------------------------------
// Kernel 0: W -> bf16 (tiny; L2-resident afterwards). grid 40 x 256.
// ---------------------------------------------------------------------------
__global__ __launch_bounds__(256)
void prep_w(const float* __restrict__ Wq, const float* __restrict__ Wk,
            const float* __restrict__ Wv)
{
    int idx = blockIdx.x * 256 + threadIdx.x;          // 0..10239
    int n = idx >> 5, cg = idx & 31;
    const float* row = (n < 32) ? Wq + n * C_
                     : (n < 64) ? Wk + (n - 32) * C_
                                : Wv + (n - 64) * C_;
    const float* p = row + cg * 8;
    uint4 o;
    o.x = pack_bf16(p[0], p[1]); o.y = pack_bf16(p[2], p[3]);
    o.z = pack_bf16(p[4], p[5]); o.w = pack_bf16(p[6], p[7]);
    g_wb4[idx] = o;
}

// ---------------------------------------------------------------------------
// Kernel 1: fused x-convert + QKV GEMM (bf16 mma.sync).
//   CTA = 64-pixel M-tile x full N=320 (5 chunks of 64). K=256.
//   A: direct LDG->cvt->STS, stored channel-major [c:256][64px] bf16 SW128
//      (one 32KB block, no staging, no extra syncs); MMA A-operand via
//      ldmatrix.x4.trans (mapping proven in R8).
//   B: R5's double-buffered 64n x 256c chunks (2 x 32KB) via cp.async.
//   Smem 97KB -> 2 CTAs/SM; 512 CTAs; warps 2(M:32px) x 4(N:16).
// ---------------------------------------------------------------------------
#define OFF_B 32768
#define GEMM_SMEM (OFF_B + 2 * 32768 + 1024)   // 99328

__global__ __launch_bounds__(256)
void qkv_mma_gemm(const float* __restrict__ x,
                  const float* __restrict__ bq, const float* __restrict__ bk,
                  const float* __restrict__ bv)
{
    extern __shared__ unsigned char dsm[];
    __shared__ float sbias[320];

    const int tid  = threadIdx.x;
    const int lane = tid & 31;
    const int wid  = tid >> 5;
    const int wm   = wid >> 2;          // 0..1 (M: 32 px each)
    const int wn   = wid & 3;           // 0..3 (N: 16 each)
    const int pix0 = blockIdx.x * 64;
    const int b    = pix0 >> 12;
    const int hw0  = pix0 & 4095;

    unsigned char* base = (unsigned char*)(((uintptr_t)dsm + 1023) & ~(uintptr_t)1023);
    const uint32_t As_u = (uint32_t)__cvta_generic_to_shared(base);
    const uint32_t Bs_u = As_u + OFF_B;

    for (int i = tid; i < 320; i += 256)
        sbias[i] = (i < 32) ? bq[i] : (i < 64) ? bk[i - 32] : bv[i - 64];

    #define ISSUE_B(nc, buf) do {                                             \
        const uint4* srcB = g_wb4 + (size_t)(nc) * 64 * 32;                   \
        uint32_t bb = Bs_u + (buf) * 32768;                                   \
        _Pragma("unroll")                                                     \
        for (int it = 0; it < 8; ++it) {                                      \
            int u = it * 256 + tid;                                           \
            int n = u >> 5, g = u & 31;                                       \
            cp16(bb + (g >> 3) * 8192 + SWZ(n * 128 + (g & 7) * 16), srcB + u);\
        }                                                                     \
        asm volatile("cp.async.commit_group;" ::: "memory");                  \
    } while (0)

    ISSUE_B(0, 0);

    // ---- A convert: x[b][c][hw0+p] fp32 -> As[c][64px] bf16 swizzled.
    // idx=(c,q): warp = 2 c-rows x 16 q -> LDG.128 coalesced (256B segments),
    // STS.64 conflict-free (half-warp covers one 128B swizzled row).
    {
        const float4* xsrc = (const float4*)(x + ((size_t)b << 20) + hw0);
        #pragma unroll
        for (int it = 0; it < 16; ++it) {
            int u = it * 256 + tid;
            int c = u >> 4, q = u & 15;
            float4 v = xsrc[(size_t)c * 1024 + q];
            uint32_t w0, w1;
            asm("cvt.rn.bf16x2.f32 %0, %1, %2;" : "=r"(w0) : "f"(v.y), "f"(v.x));
            asm("cvt.rn.bf16x2.f32 %0, %1, %2;" : "=r"(w1) : "f"(v.w), "f"(v.z));
            uint32_t dst = As_u + SWZ(c * 128 + q * 8);
            asm volatile("st.shared.v2.b32 [%0], {%1,%2};" :: "r"(dst), "r"(w0), "r"(w1) : "memory");
        }
    }
    asm volatile("cp.async.wait_group 0;" ::: "memory");
    __syncthreads();

    // ldmatrix lane-address components
    // A (trans, from [c][px] storage) — mapping proven in R8:
    const int at_c = ((lane >> 4) << 3) + (lane & 7);   // c offset within k16
    const int at_m = ((lane >> 3) & 1) << 3;            // px offset 0/8
    // B (non-trans, k-rows):
    const int b_r    = (lane & 7);
    const int b_grp  = lane >> 3;
    const int b_nrow = ((b_grp >> 1) << 3) + b_r;
    const int b_koff = (b_grp & 1) << 4;

    const int colq = (lane & 3) * 2;
    const int rowq = lane >> 2;

    for (int nc = 0; nc < 5; ++nc) {
        if (nc < 4) ISSUE_B(nc + 1, (nc + 1) & 1);
        const uint32_t Bcur = Bs_u + (nc & 1) * 32768;

        float acc[2][2][4];
        #pragma unroll
        for (int mi = 0; mi < 2; mi++)
            #pragma unroll
            for (int nj = 0; nj < 2; nj++)
                #pragma unroll
                for (int q = 0; q < 4; q++) acc[mi][nj][q] = 0.f;

        #pragma unroll
        for (int kt = 0; kt < 16; ++kt) {
            const int kchunk = kt >> 2;
            const int kb     = (kt & 3) * 32;

            uint32_t af[2][4];
            #pragma unroll
            for (int mi = 0; mi < 2; mi++) {
                int p = wm * 32 + mi * 16 + at_m;
                int c = kt * 16 + at_c;
                uint32_t ad = As_u + SWZ(c * 128 + p * 2);
                asm volatile("ldmatrix.sync.aligned.m8n8.x4.trans.shared.b16 {%0,%1,%2,%3}, [%4];"
                             : "=r"(af[mi][0]), "=r"(af[mi][1]), "=r"(af[mi][2]), "=r"(af[mi][3])
                             : "r"(ad));
            }
            uint32_t bf4[4];
            {
                int n = wn * 16 + b_nrow;
                uint32_t bd = Bcur + kchunk * 8192 + SWZ(n * 128 + kb + b_koff);
                asm volatile("ldmatrix.sync.aligned.m8n8.x4.shared.b16 {%0,%1,%2,%3}, [%4];"
                             : "=r"(bf4[0]), "=r"(bf4[1]), "=r"(bf4[2]), "=r"(bf4[3])
                             : "r"(bd));
            }
            #pragma unroll
            for (int mi = 0; mi < 2; mi++)
                #pragma unroll
                for (int nj = 0; nj < 2; nj++) {
                    asm volatile(
                        "mma.sync.aligned.m16n8k16.row.col.f32.bf16.bf16.f32 "
                        "{%0,%1,%2,%3}, {%4,%5,%6,%7}, {%8,%9}, {%0,%1,%2,%3};"
                        : "+f"(acc[mi][nj][0]), "+f"(acc[mi][nj][1]),
                          "+f"(acc[mi][nj][2]), "+f"(acc[mi][nj][3])
                        : "r"(af[mi][0]), "r"(af[mi][1]), "r"(af[mi][2]), "r"(af[mi][3]),
                          "r"(bf4[nj * 2 + 0]), "r"(bf4[nj * 2 + 1]));
                }
        }

        // Epilogue: nc==0 -> fp32 q|k; nc>=1 -> bf16x2 v
        #pragma unroll
        for (int mi = 0; mi < 2; mi++) {
            int r0 = pix0 + wm * 32 + mi * 16 + rowq;
            #pragma unroll
            for (int nj = 0; nj < 2; nj++) {
                int col = nc * 64 + wn * 16 + nj * 8 + colq;
                float bs0 = sbias[col], bs1 = sbias[col + 1];
                float v00 = acc[mi][nj][0] + bs0, v01 = acc[mi][nj][1] + bs1;
                float v10 = acc[mi][nj][2] + bs0, v11 = acc[mi][nj][3] + bs1;
                if (nc == 0) {
                    *(float2*)(g_qk + (size_t)r0 * 64 + col)       = make_float2(v00, v01);
                    *(float2*)(g_qk + (size_t)(r0 + 8) * 64 + col) = make_float2(v10, v11);
                } else {
                    int vcol2 = (col - 64) >> 1;
                    g_vb[(size_t)r0 * 128 + vcol2]       = pack_bf16(v00, v01);
                    g_vb[(size_t)(r0 + 8) * 128 + vcol2] = pack_bf16(v10, v11);
                }
            }
        }

        if (nc < 4) {
            asm volatile("cp.async.wait_group 0;" ::: "memory");
            __syncthreads();
        }
    }
}

// ---------------------------------------------------------------------------
// Kernel 2a: energies + softmax -> g_attn. Row-wide blocks (64 px), uint4
//   staging. grid (H, B) = 512 blocks. Unchanged (known-good).
// ---------------------------------------------------------------------------
#define PTILE 32
#define KCOLS 34
#define KC2   66            // 64 + 2 halo
#define EQROW 36            // floats per staged row (32 data + 4 pad)

__global__ __launch_bounds__(256)
void attn_energy(const float* __restrict__ dummy)
{
    __shared__ __align__(16) float sq[64 * EQROW];        //  9216 B
    __shared__ __align__(16) float sk[3 * KC2 * EQROW];   // 28512 B
    __shared__ __align__(16) float se[64 * 9];            //  2304 B

    const int tid    = threadIdx.x;
    const int h      = blockIdx.x;
    const int b      = blockIdx.y;
    const int pixrow = b * HW_ + h * W_;

    #pragma unroll
    for (int it = 0; it < 2; ++it) {
        int idx = it * 256 + tid;
        int p = idx >> 3, g = idx & 7;
        uint4 v = *(const uint4*)(g_qk + (size_t)(pixrow + p) * 64 + g * 4);
        *(uint4*)(sq + p * EQROW + g * 4) = v;
    }
    for (int idx = tid; idx < 3 * KC2 * 8; idx += 256) {
        int g    = idx & 7;
        int cell = idx >> 3;
        int col  = cell % KC2;
        int r    = cell / KC2;
        int hh   = h + r - 1;
        int ww   = col - 1;
        uint4 v = make_uint4(0u, 0u, 0u, 0u);
        if (hh >= 0 && hh < H_ && ww >= 0 && ww < W_)
            v = *(const uint4*)(g_qk + (size_t)(b * HW_ + hh * W_ + ww) * 64 + 32 + g * 4);
        *(uint4*)(sk + cell * EQROW + g * 4) = v;
    }
    __syncthreads();

    for (int task = tid; task < 64 * 9; task += 256) {
        int p = task / 9, j = task % 9;
        int r = j / 3, dx = j % 3;
        const float* qp = sq + p * EQROW;
        const float* kp = sk + (r * KC2 + p + dx) * EQROW;
        float e = 0.f;
        #pragma unroll
        for (int c = 0; c < 32; c++) e = fmaf(qp[c], kp[c], e);
        se[p * 9 + j] = e;
    }
    __syncthreads();

    if (tid < 64) {
        float e[9], m = -1e30f;
        #pragma unroll
        for (int j = 0; j < 9; j++) { e[j] = se[tid * 9 + j]; m = fmaxf(m, e[j]); }
        float s = 0.f;
        #pragma unroll
        for (int j = 0; j < 9; j++) { e[j] = expf(e[j] - m); s += e[j]; }
        float inv = 1.f / s;
        #pragma unroll
        for (int j = 0; j < 9; j++) se[tid * 9 + j] = e[j] * inv;
    }
    __syncthreads();

    if (tid < 144) {
        size_t base4 = (size_t)pixrow * 9 / 4;
        g_attn4[base4 + tid] = ((const uint4*)se)[tid];
    }
}

// ---------------------------------------------------------------------------
// Kernel 2b: apply weights to v + residual (unchanged, known-good 22.3us).
// ---------------------------------------------------------------------------
#define VCELL 36

__global__ __launch_bounds__(256)
void attn_apply(const float* __restrict__ x,
                const float* __restrict__ gamma,
                float* __restrict__ out)
{
    __shared__ __align__(16) uint32_t sv[3 * KCOLS * VCELL];   // 14688 B
    __shared__ __align__(16) float sa[PTILE * 9];

    const int tid   = threadIdx.x;
    const int wtile = blockIdx.x & 1;
    const int chunk = blockIdx.x >> 1;
    const int h     = blockIdx.y;
    const int b     = blockIdx.z;
    const int wbase = wtile * PTILE;
    const float g0 = gamma[0];

    const int p  = tid & 31;
    const int cg = tid >> 5;

    const size_t xbase = ((size_t)(b * C_ + chunk * 64 + cg * 8)) * HW_
                       + h * W_ + wbase + p;
    float xr[8];
    #pragma unroll
    for (int i = 0; i < 8; i++) xr[i] = x[xbase + (size_t)i * HW_];

    for (int idx = tid; idx < 3 * KCOLS * 8; idx += 256) {
        int q4   = idx & 7;
        int cell = idx >> 3;
        int col  = cell % KCOLS;
        int r    = cell / KCOLS;
        int hh   = h + r - 1;
        int ww   = wbase + col - 1;
        uint4 v = make_uint4(0u, 0u, 0u, 0u);
        if (hh >= 0 && hh < H_ && ww >= 0 && ww < W_)
            v = *(const uint4*)(g_vb + (size_t)(b * HW_ + hh * W_ + ww) * 128
                                + chunk * 32 + q4 * 4);
        *(uint4*)(sv + cell * VCELL + q4 * 4) = v;
    }
    if (tid < 72) {
        size_t base4 = (size_t)(b * HW_ + h * W_ + wbase) * 9 / 4;
        ((uint4*)sa)[tid] = g_attn4[base4 + tid];
    }
    __syncthreads();

    float a[9];
    #pragma unroll
    for (int j = 0; j < 9; j++) a[j] = sa[p * 9 + j];

    float acc[8];
    #pragma unroll
    for (int i = 0; i < 8; i++) acc[i] = 0.f;

    #pragma unroll
    for (int j = 0; j < 9; j++) {
        const uint32_t* svp = sv + ((j / 3) * KCOLS + p + (j % 3)) * VCELL + cg * 4;
        uint4 w = *(const uint4*)svp;
        float aj = a[j];
        uint32_t ws[4] = {w.x, w.y, w.z, w.w};
        #pragma unroll
        for (int u = 0; u < 4; u++) {
            float flo = __uint_as_float(ws[u] << 16);
            float fhi = __uint_as_float(ws[u] & 0xffff0000u);
            acc[2 * u + 0] = fmaf(aj, flo, acc[2 * u + 0]);
            acc[2 * u + 1] = fmaf(aj, fhi, acc[2 * u + 1]);
        }
    }

    #pragma unroll
    for (int i = 0; i < 8; i++)
        out[xbase + (size_t)i * HW_] = fmaf(g0, acc[i], xr[i]);
}

// ---------------------------------------------------------------------------
extern "C" void kernel_launch(void* const* d_in, const int* in_sizes, int n_in,
                              void* d_out, int out_size)
{
    const float* x     = (const float*)d_in[0];
    const float* Wq    = (const float*)d_in[1];
    const float* bq    = (const float*)d_in[2];
    const float* Wk    = (const float*)d_in[3];
    const float* bk    = (const float*)d_in[4];
    const float* Wv    = (const float*)d_in[5];
    const float* bv    = (const float*)d_in[6];
    const float* gamma = (const float*)d_in[7];
    float* out = (float*)d_out;

    cudaFuncSetAttribute(qkv_mma_gemm, cudaFuncAttributeMaxDynamicSharedMemorySize, GEMM_SMEM);

    prep_w<<<40, 256>>>(Wq, Wk, Wv);
    qkv_mma_gemm<<<512, 256, GEMM_SMEM>>>(x, bq, bk, bv);

    dim3 egrid(H_, B_);
    attn_energy<<<egrid, 256>>>(x);

    dim3 agrid(8, H_, B_);
    attn_apply<<<agrid, 256>>>(x, gamma, out);
}

// round 15
// speedup vs baseline: 1.1070x; 1.1070x over previous
#include <cuda_runtime.h>
#include <cuda_bf16.h>
#include <math.h>
#include <stdint.h>

// Problem constants
#define B_  8
#define C_  256
#define H_  64
#define W_  64
#define HW_ 4096
#define NPIX 32768

// Scratch
__device__ float    g_qk[(size_t)NPIX * 64];      // fp32 q(32)|k(32), pixel-major
__device__ uint32_t g_vb[(size_t)NPIX * 128];     // bf16x2 v (256ch), pixel-major
__device__ uint4    g_wb4[320 * 32];              // bf16 W, [n][256ch], n-order q|k|v
__device__ uint4    g_attn4[(size_t)NPIX * 9 / 4]; // softmaxed weights [pix][9] fp32

#define SWZ(o) ((o) ^ (((o) >> 3) & 0x70))

__device__ __forceinline__ uint32_t pack_bf16(float lo, float hi) {
    uint32_t l = (uint32_t)__bfloat16_as_ushort(__float2bfloat16_rn(lo));
    uint32_t h = (uint32_t)__bfloat16_as_ushort(__float2bfloat16_rn(hi));
    return (h << 16) | l;
}

__device__ __forceinline__ void cp16(uint32_t dst, const void* src) {
    asm volatile("cp.async.cg.shared.global [%0], [%1], 16;" :: "r"(dst), "l"(src) : "memory");
}

// ---------------------------------------------------------------------------
// Kernel 0: W -> bf16 (tiny; L2-resident afterwards). grid 40 x 256.
// ---------------------------------------------------------------------------
__global__ __launch_bounds__(256)
void prep_w(const float* __restrict__ Wq, const float* __restrict__ Wk,
            const float* __restrict__ Wv)
{
    int idx = blockIdx.x * 256 + threadIdx.x;          // 0..10239
    int n = idx >> 5, cg = idx & 31;
    const float* row = (n < 32) ? Wq + n * C_
                     : (n < 64) ? Wk + (n - 32) * C_
                                : Wv + (n - 64) * C_;
    const float* p = row + cg * 8;
    uint4 o;
    o.x = pack_bf16(p[0], p[1]); o.y = pack_bf16(p[2], p[3]);
    o.z = pack_bf16(p[4], p[5]); o.w = pack_bf16(p[6], p[7]);
    g_wb4[idx] = o;
}

// ---------------------------------------------------------------------------
// Kernel 1: fused x-convert + QKV GEMM (bf16 mma.sync).
//   CTA = 128-pixel M-tile x full N=320 (5 chunks of 64). K=256.
//   A: direct LDG->cvt->STS (no fp32 staging, 1 sync), stored channel-major
//      [half(px>=64)][c:256][64px] bf16 SW128; MMA A via ldmatrix.x4.trans
//      (mapping + numerics proven bit-identical in R12).
//   B: R5's double-buffered 64n x 256c chunks (2 x 32KB) via cp.async,
//      prefetch overlapping the mainloop. 4M x 2N warps, acc 32x32 per warp.
//   Smem 132KB -> 1 CTA/SM, 256 CTAs.
// ---------------------------------------------------------------------------
#define OFF_B 65536
#define GEMM_SMEM (OFF_B + 2 * 32768 + 1024)   // 132096

__global__ __launch_bounds__(256)
void qkv_mma_gemm(const float* __restrict__ x,
                  const float* __restrict__ bq, const float* __restrict__ bk,
                  const float* __restrict__ bv)
{
    extern __shared__ unsigned char dsm[];
    __shared__ float sbias[320];

    const int tid  = threadIdx.x;
    const int lane = tid & 31;
    const int wid  = tid >> 5;
    const int wm   = wid >> 1;          // 0..3 (M: 32 px each)
    const int wn   = wid & 1;           // 0..1 (N: 32 each)
    const int pix0 = blockIdx.x * 128;
    const int b    = pix0 >> 12;
    const int hw0  = pix0 & 4095;

    unsigned char* base = (unsigned char*)(((uintptr_t)dsm + 1023) & ~(uintptr_t)1023);
    const uint32_t As_u = (uint32_t)__cvta_generic_to_shared(base);
    const uint32_t Bs_u = As_u + OFF_B;

    for (int i = tid; i < 320; i += 256)
        sbias[i] = (i < 32) ? bq[i] : (i < 64) ? bk[i - 32] : bv[i - 64];

    #define ISSUE_B(nc, buf) do {                                             \
        const uint4* srcB = g_wb4 + (size_t)(nc) * 64 * 32;                   \
        uint32_t bb = Bs_u + (buf) * 32768;                                   \
        _Pragma("unroll")                                                     \
        for (int it = 0; it < 8; ++it) {                                      \
            int u = it * 256 + tid;                                           \
            int n = u >> 5, g = u & 31;                                       \
            cp16(bb + (g >> 3) * 8192 + SWZ(n * 128 + (g & 7) * 16), srcB + u);\
        }                                                                     \
        asm volatile("cp.async.commit_group;" ::: "memory");                  \
    } while (0)

    ISSUE_B(0, 0);

    // ---- A convert: x[b][c][hw0+p] fp32 -> As[half][c:256][64px] bf16 SW128.
    // Warp covers one c-row of 128 px: LDG.128 coalesced (512B), STS.64
    // conflict-free (16 lanes span one swizzled 128B row per half).
    {
        const float4* xsrc = (const float4*)(x + ((size_t)b << 20) + hw0);
        #pragma unroll
        for (int it = 0; it < 32; ++it) {
            int u = it * 256 + tid;
            int c = u >> 5, q = u & 31;
            float4 v = xsrc[(size_t)c * 1024 + q];
            uint32_t w0, w1;
            asm("cvt.rn.bf16x2.f32 %0, %1, %2;" : "=r"(w0) : "f"(v.y), "f"(v.x));
            asm("cvt.rn.bf16x2.f32 %0, %1, %2;" : "=r"(w1) : "f"(v.w), "f"(v.z));
            int p0 = q * 4;
            uint32_t dst = As_u + ((p0 >> 6) << 15) + SWZ(c * 128 + (p0 & 63) * 2);
            asm volatile("st.shared.v2.b32 [%0], {%1,%2};" :: "r"(dst), "r"(w0), "r"(w1) : "memory");
        }
    }
    asm volatile("cp.async.wait_group 0;" ::: "memory");
    __syncthreads();

    // ldmatrix lane-address components
    // A (trans, from [c][px] storage) — R12-proven mapping:
    const int at_c = ((lane >> 4) << 3) + (lane & 7);   // c offset within k16
    const int at_m = ((lane >> 3) & 1) << 3;            // px offset 0/8
    // B (non-trans, k-rows): R5's
    const int b_r    = (lane & 7);
    const int b_grp  = lane >> 3;
    const int b_nrow = ((b_grp >> 1) << 3) + b_r;
    const int b_koff = (b_grp & 1) << 4;

    for (int nc = 0; nc < 5; ++nc) {
        if (nc < 4) ISSUE_B(nc + 1, (nc + 1) & 1);
        const uint32_t Bcur = Bs_u + (nc & 1) * 32768;

        float acc[2][4][4];
        #pragma unroll
        for (int mi = 0; mi < 2; mi++)
            #pragma unroll
            for (int nj = 0; nj < 4; nj++)
                #pragma unroll
                for (int q = 0; q < 4; q++) acc[mi][nj][q] = 0.f;

        #pragma unroll
        for (int kt = 0; kt < 16; ++kt) {
            const int chunk = kt >> 2;
            const int kb    = (kt & 3) * 32;

            uint32_t af[2][4];
            #pragma unroll
            for (int mi = 0; mi < 2; mi++) {
                int p = wm * 32 + mi * 16 + at_m;
                int c = kt * 16 + at_c;
                uint32_t ad = As_u + ((p >> 6) << 15) + SWZ(c * 128 + (p & 63) * 2);
                asm volatile("ldmatrix.sync.aligned.m8n8.x4.trans.shared.b16 {%0,%1,%2,%3}, [%4];"
                             : "=r"(af[mi][0]), "=r"(af[mi][1]), "=r"(af[mi][2]), "=r"(af[mi][3])
                             : "r"(ad));
            }
            uint32_t bf[2][4];
            #pragma unroll
            for (int njp = 0; njp < 2; njp++) {
                int n = wn * 32 + njp * 16 + b_nrow;
                uint32_t bd = Bcur + chunk * 8192 + SWZ(n * 128 + kb + b_koff);
                asm volatile("ldmatrix.sync.aligned.m8n8.x4.shared.b16 {%0,%1,%2,%3}, [%4];"
                             : "=r"(bf[njp][0]), "=r"(bf[njp][1]), "=r"(bf[njp][2]), "=r"(bf[njp][3])
                             : "r"(bd));
            }
            #pragma unroll
            for (int mi = 0; mi < 2; mi++)
                #pragma unroll
                for (int nj = 0; nj < 4; nj++) {
                    uint32_t b0 = bf[nj >> 1][(nj & 1) * 2 + 0];
                    uint32_t b1 = bf[nj >> 1][(nj & 1) * 2 + 1];
                    asm volatile(
                        "mma.sync.aligned.m16n8k16.row.col.f32.bf16.bf16.f32 "
                        "{%0,%1,%2,%3}, {%4,%5,%6,%7}, {%8,%9}, {%0,%1,%2,%3};"
                        : "+f"(acc[mi][nj][0]), "+f"(acc[mi][nj][1]),
                          "+f"(acc[mi][nj][2]), "+f"(acc[mi][nj][3])
                        : "r"(af[mi][0]), "r"(af[mi][1]), "r"(af[mi][2]), "r"(af[mi][3]),
                          "r"(b0), "r"(b1));
                }
        }

        // Epilogue: nc==0 -> fp32 q|k; nc>=1 -> bf16x2 v
        {
            const int colq = (lane & 3) * 2;
            const int rowq = lane >> 2;
            #pragma unroll
            for (int mi = 0; mi < 2; mi++) {
                int r0 = pix0 + wm * 32 + mi * 16 + rowq;
                #pragma unroll
                for (int nj = 0; nj < 4; nj++) {
                    int col = nc * 64 + wn * 32 + nj * 8 + colq;
                    float bs0 = sbias[col], bs1 = sbias[col + 1];
                    float v00 = acc[mi][nj][0] + bs0, v01 = acc[mi][nj][1] + bs1;
                    float v10 = acc[mi][nj][2] + bs0, v11 = acc[mi][nj][3] + bs1;
                    if (nc == 0) {
                        *(float2*)(g_qk + (size_t)r0 * 64 + col)       = make_float2(v00, v01);
                        *(float2*)(g_qk + (size_t)(r0 + 8) * 64 + col) = make_float2(v10, v11);
                    } else {
                        int vcol2 = (col - 64) >> 1;
                        g_vb[(size_t)r0 * 128 + vcol2]       = pack_bf16(v00, v01);
                        g_vb[(size_t)(r0 + 8) * 128 + vcol2] = pack_bf16(v10, v11);
                    }
                }
            }
        }

        if (nc < 4) {
            asm volatile("cp.async.wait_group 0;" ::: "memory");
            __syncthreads();
        }
    }
}

// ---------------------------------------------------------------------------
// Kernel 2a: energies + softmax -> g_attn. Row-wide blocks (64 px), uint4
//   staging. grid (H, B) = 512 blocks. Unchanged (known-good).
// ---------------------------------------------------------------------------
#define PTILE 32
#define KCOLS 34
#define KC2   66            // 64 + 2 halo
#define EQROW 36            // floats per staged row (32 data + 4 pad)

__global__ __launch_bounds__(256)
void attn_energy(const float* __restrict__ dummy)
{
    __shared__ __align__(16) float sq[64 * EQROW];        //  9216 B
    __shared__ __align__(16) float sk[3 * KC2 * EQROW];   // 28512 B
    __shared__ __align__(16) float se[64 * 9];            //  2304 B

    const int tid    = threadIdx.x;
    const int h      = blockIdx.x;
    const int b      = blockIdx.y;
    const int pixrow = b * HW_ + h * W_;

    #pragma unroll
    for (int it = 0; it < 2; ++it) {
        int idx = it * 256 + tid;
        int p = idx >> 3, g = idx & 7;
        uint4 v = *(const uint4*)(g_qk + (size_t)(pixrow + p) * 64 + g * 4);
        *(uint4*)(sq + p * EQROW + g * 4) = v;
    }
    for (int idx = tid; idx < 3 * KC2 * 8; idx += 256) {
        int g    = idx & 7;
        int cell = idx >> 3;
        int col  = cell % KC2;
        int r    = cell / KC2;
        int hh   = h + r - 1;
        int ww   = col - 1;
        uint4 v = make_uint4(0u, 0u, 0u, 0u);
        if (hh >= 0 && hh < H_ && ww >= 0 && ww < W_)
            v = *(const uint4*)(g_qk + (size_t)(b * HW_ + hh * W_ + ww) * 64 + 32 + g * 4);
        *(uint4*)(sk + cell * EQROW + g * 4) = v;
    }
    __syncthreads();

    for (int task = tid; task < 64 * 9; task += 256) {
        int p = task / 9, j = task % 9;
        int r = j / 3, dx = j % 3;
        const float* qp = sq + p * EQROW;
        const float* kp = sk + (r * KC2 + p + dx) * EQROW;
        float e = 0.f;
        #pragma unroll
        for (int c = 0; c < 32; c++) e = fmaf(qp[c], kp[c], e);
        se[p * 9 + j] = e;
    }
    __syncthreads();

    if (tid < 64) {
        float e[9], m = -1e30f;
        #pragma unroll
        for (int j = 0; j < 9; j++) { e[j] = se[tid * 9 + j]; m = fmaxf(m, e[j]); }
        float s = 0.f;
        #pragma unroll
        for (int j = 0; j < 9; j++) { e[j] = expf(e[j] - m); s += e[j]; }
        float inv = 1.f / s;
        #pragma unroll
        for (int j = 0; j < 9; j++) se[tid * 9 + j] = e[j] * inv;
    }
    __syncthreads();

    if (tid < 144) {
        size_t base4 = (size_t)pixrow * 9 / 4;
        g_attn4[base4 + tid] = ((const uint4*)se)[tid];
    }
}

// ---------------------------------------------------------------------------
// Kernel 2b: apply weights to v + residual (unchanged, known-good ~22us).
// ---------------------------------------------------------------------------
#define VCELL 36

__global__ __launch_bounds__(256)
void attn_apply(const float* __restrict__ x,
                const float* __restrict__ gamma,
                float* __restrict__ out)
{
    __shared__ __align__(16) uint32_t sv[3 * KCOLS * VCELL];   // 14688 B
    __shared__ __align__(16) float sa[PTILE * 9];

    const int tid   = threadIdx.x;
    const int wtile = blockIdx.x & 1;
    const int chunk = blockIdx.x >> 1;
    const int h     = blockIdx.y;
    const int b     = blockIdx.z;
    const int wbase = wtile * PTILE;
    const float g0 = gamma[0];

    const int p  = tid & 31;
    const int cg = tid >> 5;

    const size_t xbase = ((size_t)(b * C_ + chunk * 64 + cg * 8)) * HW_
                       + h * W_ + wbase + p;
    float xr[8];
    #pragma unroll
    for (int i = 0; i < 8; i++) xr[i] = x[xbase + (size_t)i * HW_];

    for (int idx = tid; idx < 3 * KCOLS * 8; idx += 256) {
        int q4   = idx & 7;
        int cell = idx >> 3;
        int col  = cell % KCOLS;
        int r    = cell / KCOLS;
        int hh   = h + r - 1;
        int ww   = wbase + col - 1;
        uint4 v = make_uint4(0u, 0u, 0u, 0u);
        if (hh >= 0 && hh < H_ && ww >= 0 && ww < W_)
            v = *(const uint4*)(g_vb + (size_t)(b * HW_ + hh * W_ + ww) * 128
                                + chunk * 32 + q4 * 4);
        *(uint4*)(sv + cell * VCELL + q4 * 4) = v;
    }
    if (tid < 72) {
        size_t base4 = (size_t)(b * HW_ + h * W_ + wbase) * 9 / 4;
        ((uint4*)sa)[tid] = g_attn4[base4 + tid];
    }
    __syncthreads();

    float a[9];
    #pragma unroll
    for (int j = 0; j < 9; j++) a[j] = sa[p * 9 + j];

    float acc[8];
    #pragma unroll
    for (int i = 0; i < 8; i++) acc[i] = 0.f;

    #pragma unroll
    for (int j = 0; j < 9; j++) {
        const uint32_t* svp = sv + ((j / 3) * KCOLS + p + (j % 3)) * VCELL + cg * 4;
        uint4 w = *(const uint4*)svp;
        float aj = a[j];
        uint32_t ws[4] = {w.x, w.y, w.z, w.w};
        #pragma unroll
        for (int u = 0; u < 4; u++) {
            float flo = __uint_as_float(ws[u] << 16);
            float fhi = __uint_as_float(ws[u] & 0xffff0000u);
            acc[2 * u + 0] = fmaf(aj, flo, acc[2 * u + 0]);
            acc[2 * u + 1] = fmaf(aj, fhi, acc[2 * u + 1]);
        }
    }

    #pragma unroll
    for (int i = 0; i < 8; i++)
        out[xbase + (size_t)i * HW_] = fmaf(g0, acc[i], xr[i]);
}

// ---------------------------------------------------------------------------
extern "C" void kernel_launch(void* const* d_in, const int* in_sizes, int n_in,
                              void* d_out, int out_size)
{
    const float* x     = (const float*)d_in[0];
    const float* Wq    = (const float*)d_in[1];
    const float* bq    = (const float*)d_in[2];
    const float* Wk    = (const float*)d_in[3];
    const float* bk    = (const float*)d_in[4];
    const float* Wv    = (const float*)d_in[5];
    const float* bv    = (const float*)d_in[6];
    const float* gamma = (const float*)d_in[7];
    float* out = (float*)d_out;

    cudaFuncSetAttribute(qkv_mma_gemm, cudaFuncAttributeMaxDynamicSharedMemorySize, GEMM_SMEM);

    prep_w<<<40, 256>>>(Wq, Wk, Wv);
    qkv_mma_gemm<<<256, 256, GEMM_SMEM>>>(x, bq, bk, bv);

    dim3 egrid(H_, B_);
    attn_energy<<<egrid, 256>>>(x);

    dim3 agrid(8, H_, B_);
    attn_apply<<<agrid, 256>>>(x, gamma, out);
}